// round 5
// baseline (speedup 1.0000x reference)
#include <cuda_runtime.h>

// DegreePrediction: y[u] = sum_{s,t,v} (x*W_t)[s,t] * (W_r*r_zeros + r_const)[s,t,u,v]
// N = 80. Three 80^4 fp32 tensors (491.5 MB) streamed once.
//
// R5: replace per-warp LDG streaming with cp.async.bulk (TMA engine) into a
// 5-stage SMEM ring. R1/R2/R4 all pinned 5.45-5.53 TB/s across occupancy
// 43%/84%/56% and forced-MLP variants -> the LDG path is demand-insensitive.
// Bulk-async issues 5KB contiguous requests and bypasses LDG issue/L1tex
// return entirely; tests whether the 5.5 TB/s wall is the path or the DRAM.

#define NN 80
#define SLICE_FLOATS (NN * NN)        // 6400
#define THREADS 320
#define K_SLICES 4
#define NUM_BLOCKS ((NN * NN) / K_SLICES)   // 1600
#define J_ITERS 5
#define NCHUNK (K_SLICES * J_ITERS)   // 20 chunks per block
#define CHUNK_F4 320                  // float4 per tensor per chunk (= THREADS)
#define CHUNK_BYTES (CHUNK_F4 * 16)   // 5120
#define STAGES 5
#define SMEM_BYTES (STAGES * 3 * CHUNK_BYTES)  // 76800

__device__ __forceinline__ unsigned smem_u32(const void* p) {
    unsigned a;
    asm("{ .reg .u64 t; cvta.to.shared.u64 t, %1; cvt.u32.u64 %0, t; }"
        : "=r"(a) : "l"(p));
    return a;
}
__device__ __forceinline__ void mbar_init(unsigned m, unsigned cnt) {
    asm volatile("mbarrier.init.shared.b64 [%0], %1;" :: "r"(m), "r"(cnt) : "memory");
}
__device__ __forceinline__ void mbar_expect_tx(unsigned m, unsigned bytes) {
    asm volatile("mbarrier.arrive.expect_tx.shared.b64 _, [%0], %1;"
                 :: "r"(m), "r"(bytes) : "memory");
}
__device__ __forceinline__ void bulk_g2s(unsigned dst, const void* src,
                                         unsigned bytes, unsigned mbar) {
    asm volatile(
        "cp.async.bulk.shared::cluster.global.mbarrier::complete_tx::bytes "
        "[%0], [%1], %2, [%3];"
        :: "r"(dst), "l"(src), "r"(bytes), "r"(mbar) : "memory");
}
__device__ __forceinline__ void mbar_wait(unsigned m, unsigned parity) {
    unsigned done;
    asm volatile(
        "{ .reg .pred p; mbarrier.try_wait.parity.acquire.cta.shared::cta.b64 p, [%1], %2;"
        " selp.b32 %0, 1, 0, p; }"
        : "=r"(done) : "r"(m), "r"(parity) : "memory");
    if (!done) {
        asm volatile(
            "{ .reg .pred P1;\n"
            "WAIT_LOOP_%=:\n"
            " mbarrier.try_wait.parity.acquire.cta.shared::cta.b64 P1, [%0], %1, 0x989680;\n"
            " @P1 bra.uni WAIT_DONE_%=;\n"
            " bra.uni WAIT_LOOP_%=;\n"
            "WAIT_DONE_%=: }"
            :: "r"(m), "r"(parity) : "memory");
    }
}

__global__ void zero_out_kernel(float* __restrict__ out) {
    int i = threadIdx.x;
    if (i < NN) out[i] = 0.0f;
}

extern __shared__ __align__(16) float4 dynbuf[];   // [STAGES][3][CHUNK_F4]

__global__ __launch_bounds__(THREADS, 2)
void degree_pred_kernel(const float* __restrict__ x,
                        const float* __restrict__ r_zeros,
                        const float* __restrict__ r_const,
                        const float* __restrict__ weights_t,
                        const float* __restrict__ weights_r,
                        float* __restrict__ out)
{
    __shared__ float y_sh[NN];
    __shared__ __align__(8) unsigned long long mbar_store[STAGES];

    const int tid = threadIdx.x;
    if (tid < NN) y_sh[tid] = 0.0f;

    const unsigned mb = smem_u32(&mbar_store[0]);
    const unsigned buf = smem_u32(&dynbuf[0]);

    if (tid == 0) {
#pragma unroll
        for (int s = 0; s < STAGES; s++) mbar_init(mb + s * 8, 1);
        asm volatile("fence.proxy.async.shared::cta;" ::: "memory");
    }
    __syncthreads();

    const int st0 = blockIdx.x * K_SLICES;
    float a[K_SLICES];
#pragma unroll
    for (int k = 0; k < K_SLICES; k++)
        a[k] = __ldg(&x[st0 + k]) * __ldg(&weights_t[st0 + k]);

    const size_t base_f = (size_t)st0 * SLICE_FLOATS;
    const char* srcz = (const char*)(r_zeros   + base_f);
    const char* srcc = (const char*)(r_const   + base_f);
    const char* srcw = (const char*)(weights_r + base_f);

    // prologue: fill all STAGES slots
    if (tid == 0) {
#pragma unroll
        for (int s = 0; s < STAGES; s++) {
            const unsigned m = mb + s * 8;
            mbar_expect_tx(m, 3 * CHUNK_BYTES);
            const size_t off = (size_t)s * CHUNK_BYTES;
            bulk_g2s(buf + (s * 3 + 0) * CHUNK_BYTES, srcz + off, CHUNK_BYTES, m);
            bulk_g2s(buf + (s * 3 + 1) * CHUNK_BYTES, srcc + off, CHUNK_BYTES, m);
            bulk_g2s(buf + (s * 3 + 2) * CHUNK_BYTES, srcw + off, CHUNK_BYTES, m);
        }
    }

    float acc[J_ITERS];
#pragma unroll
    for (int j = 0; j < J_ITERS; j++) acc[j] = 0.0f;

#pragma unroll
    for (int ch = 0; ch < NCHUNK; ch++) {
        const int slot = ch % STAGES;
        const int parity = (ch / STAGES) & 1;
        mbar_wait(mb + slot * 8, (unsigned)parity);

        const float4* b = dynbuf + (size_t)slot * 3 * CHUNK_F4;
        const float4 z = b[tid];
        const float4 c = b[CHUNK_F4 + tid];
        const float4 w = b[2 * CHUNK_F4 + tid];
        float t = (c.x + c.y) + (c.z + c.w);
        t = fmaf(w.x, z.x, t);
        t = fmaf(w.y, z.y, t);
        t = fmaf(w.z, z.z, t);
        t = fmaf(w.w, z.w, t);
        acc[ch % J_ITERS] = fmaf(a[ch / J_ITERS], t, acc[ch % J_ITERS]);

        __syncthreads();   // everyone done reading this slot

        const int chn = ch + STAGES;
        if (chn < NCHUNK && tid == 0) {
            const unsigned m = mb + slot * 8;
            mbar_expect_tx(m, 3 * CHUNK_BYTES);
            const size_t off = (size_t)chn * CHUNK_BYTES;
            bulk_g2s(buf + (slot * 3 + 0) * CHUNK_BYTES, srcz + off, CHUNK_BYTES, m);
            bulk_g2s(buf + (slot * 3 + 1) * CHUNK_BYTES, srcc + off, CHUNK_BYTES, m);
            bulk_g2s(buf + (slot * 3 + 2) * CHUNK_BYTES, srcw + off, CHUNK_BYTES, m);
        }
    }

    const int u0 = tid / 20;   // 20 float4 per u-row
#pragma unroll
    for (int j = 0; j < J_ITERS; j++) {
        atomicAdd(&y_sh[u0 + 16 * j], acc[j]);
    }

    __syncthreads();
    if (tid < NN) atomicAdd(&out[tid], y_sh[tid]);
}

extern "C" void kernel_launch(void* const* d_in, const int* in_sizes, int n_in,
                              void* d_out, int out_size)
{
    const float* x         = (const float*)d_in[0];
    const float* r_zeros   = (const float*)d_in[1];
    const float* r_const   = (const float*)d_in[2];
    const float* weights_t = (const float*)d_in[3];
    const float* weights_r = (const float*)d_in[4];
    float* out = (float*)d_out;

    cudaFuncSetAttribute(degree_pred_kernel,
                         cudaFuncAttributeMaxDynamicSharedMemorySize, SMEM_BYTES);

    zero_out_kernel<<<1, 128>>>(out);
    degree_pred_kernel<<<NUM_BLOCKS, THREADS, SMEM_BYTES>>>(x, r_zeros, r_const,
                                                            weights_t, weights_r, out);
}

// round 6
// speedup vs baseline: 1.0216x; 1.0216x over previous
#include <cuda_runtime.h>

// DegreePrediction: y[u] = sum_{s,t,v} (x*W_t)[s,t] * (W_r*r_zeros + r_const)[s,t,u,v]
// N = 80. Three 80^4 fp32 tensors (491.5 MB) streamed once.
//
// R6: the streaming loop is at the hardware floor (R2/R4/R5: LDG high-occ,
// forced-MLP pipeline, and TMA all pin 5.48-5.53 TB/s; kernel 90.4us ~= 99%
// of 491.5MB/5.5TB/s). Remaining gain is the serialized zero_out launch
// (~2us of the 92.4us total). Fuse it: accumulate into a persistent
// __device__ scratch, last block (atomic-counter detect) writes d_out and
// self-resets scratch+counter so each replay starts clean (graph-safe,
// deterministic, no allocations).

#define NN 80
#define SLICE_FLOATS (NN * NN)      // 6400
#define THREADS 320
#define J_ITERS 5
#define K_SLICES 4
#define NUM_BLOCKS ((NN * NN) / K_SLICES)   // 1600

__device__ float    g_scratch[NN];   // zero-initialized at module load; kernel keeps it net-zero
__device__ unsigned g_count;         // ditto

__global__ __launch_bounds__(THREADS, 4)
void degree_pred_kernel(const float* __restrict__ x,
                        const float* __restrict__ r_zeros,
                        const float* __restrict__ r_const,
                        const float* __restrict__ weights_t,
                        const float* __restrict__ weights_r,
                        float* __restrict__ out)
{
    __shared__ float y_sh[NN];
    __shared__ bool is_last;
    const int tid = threadIdx.x;
    if (tid < NN) y_sh[tid] = 0.0f;

    const int st0 = blockIdx.x * K_SLICES;

    // per-slice scalars, hoisted
    float a[K_SLICES];
#pragma unroll
    for (int k = 0; k < K_SLICES; k++)
        a[k] = __ldg(&x[st0 + k]) * __ldg(&weights_t[st0 + k]);

    float acc[J_ITERS];
#pragma unroll
    for (int j = 0; j < J_ITERS; j++) acc[j] = 0.0f;

    const size_t base0 = (size_t)st0 * SLICE_FLOATS;
    const float4* __restrict__ rz0 = reinterpret_cast<const float4*>(r_zeros   + base0);
    const float4* __restrict__ rc0 = reinterpret_cast<const float4*>(r_const   + base0);
    const float4* __restrict__ wr0 = reinterpret_cast<const float4*>(weights_r + base0);

    const int QPS = SLICE_FLOATS / 4;   // 1600 float4 per slice

    // ---- software pipeline: prefetch iteration it+1 while computing it ----
    float4 z0 = __ldcs(&rz0[tid]);
    float4 c0 = __ldcs(&rc0[tid]);
    float4 w0 = __ldcs(&wr0[tid]);

#pragma unroll
    for (int it = 0; it < K_SLICES * J_ITERS; it++) {
        const int k = it / J_ITERS;
        const int j = it % J_ITERS;

        float4 z1, c1, w1;
        if (it < K_SLICES * J_ITERS - 1) {
            const int itn = it + 1;
            const int pn = tid + THREADS * (itn % J_ITERS) + QPS * (itn / J_ITERS);
            z1 = __ldcs(&rz0[pn]);
            c1 = __ldcs(&rc0[pn]);
            w1 = __ldcs(&wr0[pn]);
        }

        float t = (c0.x + c0.y) + (c0.z + c0.w);
        t = fmaf(w0.x, z0.x, t);
        t = fmaf(w0.y, z0.y, t);
        t = fmaf(w0.z, z0.z, t);
        t = fmaf(w0.w, z0.w, t);
        acc[j] = fmaf(a[k], t, acc[j]);

        z0 = z1; c0 = c1; w0 = w1;
    }

    __syncthreads();

    const int u0 = tid / 20;   // 20 float4 per u-row
#pragma unroll
    for (int j = 0; j < J_ITERS; j++) {
        atomicAdd(&y_sh[u0 + 16 * j], acc[j]);
    }

    __syncthreads();
    if (tid < NN) atomicAdd(&g_scratch[tid], y_sh[tid]);

    // ---- last-block finalize: copy scratch -> out, reset state ----
    __threadfence();                       // order scratch adds before counter
    if (tid == 0) {
        unsigned old = atomicAdd(&g_count, 1u);
        is_last = (old == (unsigned)(NUM_BLOCKS - 1));
    }
    __syncthreads();

    if (is_last) {
        __threadfence();                   // see all blocks' scratch adds
        if (tid < NN) {
            float v = __ldcg(&g_scratch[tid]);   // L2, bypass stale L1
            out[tid] = v;
            g_scratch[tid] = 0.0f;               // restore initial state
        }
        __threadfence();
        if (tid == 0) g_count = 0u;              // restore initial state
    }
}

extern "C" void kernel_launch(void* const* d_in, const int* in_sizes, int n_in,
                              void* d_out, int out_size)
{
    const float* x         = (const float*)d_in[0];
    const float* r_zeros   = (const float*)d_in[1];
    const float* r_const   = (const float*)d_in[2];
    const float* weights_t = (const float*)d_in[3];
    const float* weights_r = (const float*)d_in[4];
    float* out = (float*)d_out;

    degree_pred_kernel<<<NUM_BLOCKS, THREADS>>>(x, r_zeros, r_const,
                                                weights_t, weights_r, out);
}

// round 7
// speedup vs baseline: 1.2391x; 1.2129x over previous
#include <cuda_runtime.h>

// DegreePrediction: y[u] = sum_{s,t,v} (x*W_t)[s,t] * (W_r*r_zeros + r_const)[s,t,u,v]
// N = 80. Three 80^4 fp32 tensors (491.5 MB) streamed once.
//
// R7: R4 mainloop (measured fastest: 90.37us kernel @ 5.53 TB/s, which four
// independent mechanisms showed to be the pattern ceiling) + fused finalize
// with a CHEAP epilogue:
//   - plain STS transpose + 80-thread gather instead of conflicting smem atomics
//   - single atom.add.acq_rel.gpu counter instead of __threadfence (R6's
//     MEMBAR.GPU/L1-flush per block cost ~4us)
//   - last block copies scratch->out and self-resets state (graph-safe).

#define NN 80
#define SLICE_FLOATS (NN * NN)      // 6400
#define THREADS 320
#define J_ITERS 5
#define K_SLICES 4
#define NUM_BLOCKS ((NN * NN) / K_SLICES)   // 1600

__device__ float    g_scratch[NN];   // zero at load; kernel keeps it net-zero
__device__ unsigned g_count;         // ditto

__device__ __forceinline__ unsigned atom_inc_acq_rel(unsigned* p) {
    unsigned old;
    asm volatile("atom.add.acq_rel.gpu.global.u32 %0, [%1], 1;"
                 : "=r"(old) : "l"(p) : "memory");
    return old;
}

__global__ __launch_bounds__(THREADS, 4)
void degree_pred_kernel(const float* __restrict__ x,
                        const float* __restrict__ r_zeros,
                        const float* __restrict__ r_const,
                        const float* __restrict__ weights_t,
                        const float* __restrict__ weights_r,
                        float* __restrict__ out)
{
    __shared__ float y_part[J_ITERS][THREADS];
    __shared__ bool is_last;
    const int tid = threadIdx.x;

    const int st0 = blockIdx.x * K_SLICES;

    // per-slice scalars, hoisted
    float a[K_SLICES];
#pragma unroll
    for (int k = 0; k < K_SLICES; k++)
        a[k] = __ldg(&x[st0 + k]) * __ldg(&weights_t[st0 + k]);

    float acc[J_ITERS];
#pragma unroll
    for (int j = 0; j < J_ITERS; j++) acc[j] = 0.0f;

    const size_t base0 = (size_t)st0 * SLICE_FLOATS;
    const float4* __restrict__ rz0 = reinterpret_cast<const float4*>(r_zeros   + base0);
    const float4* __restrict__ rc0 = reinterpret_cast<const float4*>(r_const   + base0);
    const float4* __restrict__ wr0 = reinterpret_cast<const float4*>(weights_r + base0);

    const int QPS = SLICE_FLOATS / 4;   // 1600 float4 per slice

    // ---- software pipeline: prefetch iteration it+1 while computing it ----
    float4 z0 = __ldcs(&rz0[tid]);
    float4 c0 = __ldcs(&rc0[tid]);
    float4 w0 = __ldcs(&wr0[tid]);

#pragma unroll
    for (int it = 0; it < K_SLICES * J_ITERS; it++) {
        const int k = it / J_ITERS;
        const int j = it % J_ITERS;

        float4 z1, c1, w1;
        if (it < K_SLICES * J_ITERS - 1) {
            const int itn = it + 1;
            const int pn = tid + THREADS * (itn % J_ITERS) + QPS * (itn / J_ITERS);
            z1 = __ldcs(&rz0[pn]);
            c1 = __ldcs(&rc0[pn]);
            w1 = __ldcs(&wr0[pn]);
        }

        float t = (c0.x + c0.y) + (c0.z + c0.w);
        t = fmaf(w0.x, z0.x, t);
        t = fmaf(w0.y, z0.y, t);
        t = fmaf(w0.z, z0.z, t);
        t = fmaf(w0.w, z0.w, t);
        acc[j] = fmaf(a[k], t, acc[j]);

        z0 = z1; c0 = c1; w0 = w1;
    }

    // ---- epilogue: conflict-free STS transpose + 80-thread gather ----
    // mainloop mapping: acc[j] belongs to u = tid/20 + 16*j
#pragma unroll
    for (int j = 0; j < J_ITERS; j++)
        y_part[j][tid] = acc[j];
    __syncthreads();

    if (tid < NN) {
        const int u = tid;
        const int j = u >> 4;            // u / 16
        const int b = (u & 15) * 20;     // first of 20 contributing threads
        float s = 0.0f;
#pragma unroll
        for (int d = 0; d < 20; d++)
            s += y_part[j][b + d];
        atomicAdd(&g_scratch[u], s);     // relaxed; published by acq_rel below
    }
    __syncthreads();

    // ---- last-block finalize (no full membar, no L1 flush) ----
    if (tid == 0)
        is_last = (atom_inc_acq_rel(&g_count) == (unsigned)(NUM_BLOCKS - 1));
    __syncthreads();

    if (is_last) {
        if (tid < NN) {
            float v = __ldcg(&g_scratch[tid]);   // L2 read, coherent w/ atomics
            out[tid] = v;
            g_scratch[tid] = 0.0f;               // restore initial state
        }
        __syncthreads();
        if (tid == 0) g_count = 0u;              // restore initial state
    }
}

extern "C" void kernel_launch(void* const* d_in, const int* in_sizes, int n_in,
                              void* d_out, int out_size)
{
    const float* x         = (const float*)d_in[0];
    const float* r_zeros   = (const float*)d_in[1];
    const float* r_const   = (const float*)d_in[2];
    const float* weights_t = (const float*)d_in[3];
    const float* weights_r = (const float*)d_in[4];
    float* out = (float*)d_out;

    degree_pred_kernel<<<NUM_BLOCKS, THREADS>>>(x, r_zeros, r_const,
                                                weights_t, weights_r, out);
}